// round 5
// baseline (speedup 1.0000x reference)
#include <cuda_runtime.h>
#include <math.h>
#include <stdint.h>

#define FULL 0xFFFFFFFFu
#define TOK_PER_WARP 4

// monotone float->u32 key: order(key) == order(float), all non-NaN
__device__ __forceinline__ unsigned f2key(float f) {
    unsigned b = __float_as_uint(f);
    return (b & 0x80000000u) ? ~b : (b | 0x80000000u);
}
__device__ __forceinline__ float key2f(unsigned k) {
    unsigned b = (k & 0x80000000u) ? (k ^ 0x80000000u) : ~k;
    return __uint_as_float(b);
}

#define CE(i, j) { unsigned a_ = s[i], b_ = s[j]; s[i] = umax(a_, b_); s[j] = umin(a_, b_); }

__global__ __launch_bounds__(128)
void topk_route_kernel(const float* __restrict__ logits,
                       const float* __restrict__ bias,
                       float* __restrict__ out, int T)
{
    const int lane = threadIdx.x & 31;
    const int warp = threadIdx.x >> 5;
    const int tb = (blockIdx.x * 4 + warp) * TOK_PER_WARP;
    if (tb >= T) return;

    const unsigned lmlt = (1u << lane) - 1u;   // lanemask_lt

    // bias: loaded once, reused for all 4 tokens
    const float4* bp = (const float4*)(bias + lane * 8);
    float4 b0 = __ldg(bp), b1 = __ldg(bp + 1);
    float bb[8] = {b0.x, b0.y, b0.z, b0.w, b1.x, b1.y, b1.z, b1.w};

    // prefetch first token's logits (lane l owns experts [8l,8l+8), group l>>2)
    const float* lg = logits + (size_t)tb * 256 + lane * 8;
    float4 x0 = *(const float4*)lg;
    float4 x1 = *(const float4*)(lg + 4);

    #pragma unroll
    for (int it = 0; it < TOK_PER_WARP; it++) {
        const int t = tb + it;
        if (t >= T) break;

        float4 cx0 = x0, cx1 = x1;
        if (it + 1 < TOK_PER_WARP && t + 1 < T) {           // prefetch next token
            const float* ln = logits + (size_t)(t + 1) * 256 + lane * 8;
            x0 = *(const float4*)ln;
            x1 = *(const float4*)(ln + 4);
        }

        // passthrough logits
        float* lo = out + (size_t)T * 16 + (size_t)t * 256 + lane * 8;
        *(float4*)lo = cx0;
        *(float4*)(lo + 4) = cx1;

        float xx[8] = {cx0.x, cx0.y, cx0.z, cx0.w, cx1.x, cx1.y, cx1.z, cx1.w};

        // sigmoid (precise: ids must be exact) + bias -> monotone keys
        unsigned orig[8], s[8];
        #pragma unroll
        for (int i = 0; i < 8; i++) {
            float si = 1.0f / (1.0f + expf(-xx[i]));
            orig[i] = f2key(si + bb[i]);
            s[i] = orig[i];
        }

        // per-lane descending sort (Batcher odd-even, 19 comparators)
        CE(0,1) CE(2,3) CE(4,5) CE(6,7)
        CE(0,2) CE(1,3) CE(4,6) CE(5,7)
        CE(1,2) CE(5,6)
        CE(0,4) CE(1,5) CE(2,6) CE(3,7)
        CE(2,4) CE(3,5)
        CE(1,2) CE(3,4) CE(5,6)

        // group score = top2 sum (per-lane top2 free from sort: s[0], s[1])
        unsigned m1 = s[0], m2 = s[1];
        #pragma unroll
        for (int off = 1; off <= 2; off <<= 1) {
            unsigned o1 = __shfl_xor_sync(FULL, m1, off);
            unsigned o2 = __shfl_xor_sync(FULL, m2, off);
            unsigned l2 = umin(m1, o1);
            m1 = umax(m1, o1);
            m2 = umax(l2, umax(m2, o2));
        }
        float gs = key2f(m1) + key2f(m2);   // identical across each quad

        // broadcast 8 group scores; lane ranks its OWN group (exact jax ties)
        float g[8];
        #pragma unroll
        for (int j = 0; j < 8; j++) g[j] = __shfl_sync(FULL, gs, j * 4);
        int grp = lane >> 2;
        int rank = 0;
        #pragma unroll
        for (int j = 0; j < 8; j++)
            rank += ((g[j] > gs) || (g[j] == gs && j < grp)) ? 1 : 0;
        bool sel = rank < 4;

        // mask unselected groups to key(0.0f)
        #pragma unroll
        for (int i = 0; i < 8; i++) s[i] = sel ? s[i] : 0x80000000u;

        // 8 extraction rounds; record ballot, decode winner lane once after
        unsigned krec = 0, brec = 0;
        #pragma unroll
        for (int r = 0; r < 8; r++) {
            unsigned kmax = __reduce_max_sync(FULL, s[0]);
            bool eq = (s[0] == kmax);
            unsigned bal = __ballot_sync(FULL, eq);
            if (lane == r) { krec = kmax; brec = bal; }
            if (r < 7) {
                bool p = eq && ((bal & lmlt) == 0u);   // I'm the lowest-lane winner
                #pragma unroll
                for (int i = 0; i < 7; i++) s[i] = p ? s[i + 1] : s[i];
            }
        }
        int wrec = __ffs((int)brec) - 1;

        // index recovery: lane k finds pos of krec in lane wrec's orig[]
        unsigned gk[8];
        #pragma unroll
        for (int i = 0; i < 8; i++) gk[i] = __shfl_sync(FULL, orig[i], wrec);
        int pos = 7;
        #pragma unroll
        for (int i = 6; i >= 0; i--) pos = (gk[i] == krec) ? i : pos;
        int gidx = (wrec << 3) + pos;

        // weight = unbiased score = biased - bias ; normalize; scale
        float w = key2f(krec) - __ldg(bias + gidx);
        float sum = w;
        sum += __shfl_xor_sync(FULL, sum, 1);
        sum += __shfl_xor_sync(FULL, sum, 2);
        sum += __shfl_xor_sync(FULL, sum, 4);
        float wn = w / sum * 2.5f;

        if (lane < 8) {
            out[(size_t)t * 8 + lane] = wn;
            out[(size_t)T * 8 + (size_t)t * 8 + lane] = (float)gidx;
        }
    }
}

extern "C" void kernel_launch(void* const* d_in, const int* in_sizes, int n_in,
                              void* d_out, int out_size)
{
    // inputs: hidden_states (unused), router_logits [T,256], correction_bias [256]
    const float* logits = (const float*)d_in[1];
    const float* bias   = (const float*)d_in[2];
    float* out = (float*)d_out;

    int T = in_sizes[1] / 256;
    int tok_per_block = 4 * TOK_PER_WARP;                 // 4 warps/block
    int blocks = (T + tok_per_block - 1) / tok_per_block; // 1024 for T=16384
    topk_route_kernel<<<blocks, 128>>>(logits, bias, out, T);
}

// round 6
// speedup vs baseline: 1.0152x; 1.0152x over previous
#include <cuda_runtime.h>
#include <math.h>
#include <stdint.h>

#define FULL 0xFFFFFFFFu
#define TOK_PER_WARP 2

// monotone float->u32 key: order(key) == order(float), all non-NaN
__device__ __forceinline__ unsigned f2key(float f) {
    unsigned b = __float_as_uint(f);
    return (b & 0x80000000u) ? ~b : (b | 0x80000000u);
}
__device__ __forceinline__ float key2f(unsigned k) {
    unsigned b = (k & 0x80000000u) ? (k ^ 0x80000000u) : ~k;
    return __uint_as_float(b);
}

#define CE(i, j) { unsigned a_ = s[i], b_ = s[j]; s[i] = umax(a_, b_); s[j] = umin(a_, b_); }

__global__ __launch_bounds__(128, 14)   // cap regs so 56 warps/SM fit -> single wave
void topk_route_kernel(const float* __restrict__ logits,
                       const float* __restrict__ bias,
                       float* __restrict__ out, int T)
{
    const int lane = threadIdx.x & 31;
    const int warp = threadIdx.x >> 5;
    const int tb = (blockIdx.x * 4 + warp) * TOK_PER_WARP;
    if (tb >= T) return;

    const unsigned lmlt = (1u << lane) - 1u;   // lanemask_lt

    // bias: loaded once, reused across both tokens
    const float4* bp = (const float4*)(bias + lane * 8);
    float4 b0 = __ldg(bp), b1 = __ldg(bp + 1);
    float bb[8] = {b0.x, b0.y, b0.z, b0.w, b1.x, b1.y, b1.z, b1.w};

    #pragma unroll
    for (int it = 0; it < TOK_PER_WARP; it++) {
        const int t = tb + it;
        if (t >= T) break;

        // lane l owns experts [8l, 8l+8); all 8 are in group l>>2
        const float* lg = logits + (size_t)t * 256 + lane * 8;
        float4 x0 = *(const float4*)lg;
        float4 x1 = *(const float4*)(lg + 4);

        // passthrough logits immediately (frees regs)
        float* lo = out + (size_t)T * 16 + (size_t)t * 256 + lane * 8;
        *(float4*)lo = x0;
        *(float4*)(lo + 4) = x1;

        float xx[8] = {x0.x, x0.y, x0.z, x0.w, x1.x, x1.y, x1.z, x1.w};

        // sigmoid (precise: ids must be exact) + bias -> monotone keys
        unsigned orig[8], s[8];
        #pragma unroll
        for (int i = 0; i < 8; i++) {
            float si = 1.0f / (1.0f + expf(-xx[i]));
            orig[i] = f2key(si + bb[i]);
            s[i] = orig[i];
        }

        // per-lane descending sort (Batcher odd-even, 19 comparators)
        CE(0,1) CE(2,3) CE(4,5) CE(6,7)
        CE(0,2) CE(1,3) CE(4,6) CE(5,7)
        CE(1,2) CE(5,6)
        CE(0,4) CE(1,5) CE(2,6) CE(3,7)
        CE(2,4) CE(3,5)
        CE(1,2) CE(3,4) CE(5,6)

        // group score = top2 sum (per-lane top2 free from sort: s[0], s[1])
        unsigned m1 = s[0], m2 = s[1];
        #pragma unroll
        for (int off = 1; off <= 2; off <<= 1) {
            unsigned o1 = __shfl_xor_sync(FULL, m1, off);
            unsigned o2 = __shfl_xor_sync(FULL, m2, off);
            unsigned l2 = umin(m1, o1);
            m1 = umax(m1, o1);
            m2 = umax(l2, umax(m2, o2));
        }
        float gs = key2f(m1) + key2f(m2);   // identical across each quad

        // broadcast 8 group scores; lane ranks its OWN group (exact jax ties)
        float g[8];
        #pragma unroll
        for (int j = 0; j < 8; j++) g[j] = __shfl_sync(FULL, gs, j * 4);
        int grp = lane >> 2;
        int rank = 0;
        #pragma unroll
        for (int j = 0; j < 8; j++)
            rank += ((g[j] > gs) || (g[j] == gs && j < grp)) ? 1 : 0;
        bool sel = rank < 4;

        // mask unselected groups to key(0.0f)
        #pragma unroll
        for (int i = 0; i < 8; i++) s[i] = sel ? s[i] : 0x80000000u;

        // 8 extraction rounds; record ballot, decode winner lane once after
        unsigned krec = 0, brec = 0;
        #pragma unroll
        for (int r = 0; r < 8; r++) {
            unsigned kmax = __reduce_max_sync(FULL, s[0]);
            bool eq = (s[0] == kmax);
            unsigned bal = __ballot_sync(FULL, eq);
            if (lane == r) { krec = kmax; brec = bal; }
            if (r < 7) {
                bool p = eq && ((bal & lmlt) == 0u);   // lowest-lane winner shifts
                #pragma unroll
                for (int i = 0; i < 7; i++) s[i] = p ? s[i + 1] : s[i];
            }
        }
        int wrec = __ffs((int)brec) - 1;

        // index recovery: lane k finds pos of krec in lane wrec's orig[]
        unsigned gk[8];
        #pragma unroll
        for (int i = 0; i < 8; i++) gk[i] = __shfl_sync(FULL, orig[i], wrec);
        int pos = 7;
        #pragma unroll
        for (int i = 6; i >= 0; i--) pos = (gk[i] == krec) ? i : pos;
        int gidx = (wrec << 3) + pos;

        // weight = unbiased score = biased - bias ; normalize; scale
        float w = key2f(krec) - __ldg(bias + gidx);
        float sum = w;
        sum += __shfl_xor_sync(FULL, sum, 1);
        sum += __shfl_xor_sync(FULL, sum, 2);
        sum += __shfl_xor_sync(FULL, sum, 4);
        float wn = w / sum * 2.5f;

        if (lane < 8) {
            out[(size_t)t * 8 + lane] = wn;
            out[(size_t)T * 8 + (size_t)t * 8 + lane] = (float)gidx;
        }
    }
}

extern "C" void kernel_launch(void* const* d_in, const int* in_sizes, int n_in,
                              void* d_out, int out_size)
{
    // inputs: hidden_states (unused), router_logits [T,256], correction_bias [256]
    const float* logits = (const float*)d_in[1];
    const float* bias   = (const float*)d_in[2];
    float* out = (float*)d_out;

    int T = in_sizes[1] / 256;
    int tok_per_block = 4 * TOK_PER_WARP;                 // 8 tokens per 128-thread block
    int blocks = (T + tok_per_block - 1) / tok_per_block; // 2048 for T=16384
    topk_route_kernel<<<blocks, 128>>>(logits, bias, out, T);
}